// round 1
// baseline (speedup 1.0000x reference)
#include <cuda_runtime.h>

#define TOKENS 16384
#define DIM    4096
#define NE     64
#define BM     64
#define BK     32
#define NTHR   128

__global__ __launch_bounds__(NTHR)
void topk_gate_kernel(const float* __restrict__ x, const float* __restrict__ W,
                      float* __restrict__ out_logits, float* __restrict__ out_scores,
                      float* __restrict__ out_loss)
{
    __shared__ float sx[BK][BM + 2];   // row = 66 floats (264B: 8B-aligned rows)
    __shared__ float sw[BK][NE + 4];   // row = 68 floats (272B: 16B-aligned rows)
    __shared__ float slog[BM][NE + 4];
    __shared__ float s_s1[BM], s_s2[BM];
    __shared__ int   s_i1[BM], s_i2[BM];

    const int tid    = threadIdx.x;
    const int m_base = blockIdx.x * BM;
    const int ty = tid >> 4;          // 0..7  -> m group
    const int tx = tid & 15;          // 0..15 -> n group
    const int m0 = ty * 8;            // 8 tokens per thread
    const int n0 = tx * 4;            // 4 experts per thread

    // tile-load mapping: 16 rows x 8 float4-columns per pass, 4 passes
    const int lrow = tid >> 3;            // 0..15
    const int lk4  = (tid & 7) * 4;       // 0,4,...,28

    unsigned long long acc[4][4];         // [n][m-pair], f32x2 packed
    #pragma unroll
    for (int j = 0; j < 4; j++)
        #pragma unroll
        for (int p = 0; p < 4; p++) acc[j][p] = 0ull;

    const float* xg = x + (size_t)m_base * DIM;

    for (int k0 = 0; k0 < DIM; k0 += BK) {
        // ---- stage x tile transposed: sx[k][m] ----
        #pragma unroll
        for (int r = 0; r < 4; r++) {
            int row = r * 16 + lrow;
            float4 v = *reinterpret_cast<const float4*>(&xg[(size_t)row * DIM + k0 + lk4]);
            sx[lk4 + 0][row] = v.x;
            sx[lk4 + 1][row] = v.y;
            sx[lk4 + 2][row] = v.z;
            sx[lk4 + 3][row] = v.w;
        }
        // ---- stage W tile transposed: sw[k][n] ----
        #pragma unroll
        for (int r = 0; r < 4; r++) {
            int row = r * 16 + lrow;
            float4 v = *reinterpret_cast<const float4*>(&W[(size_t)row * DIM + k0 + lk4]);
            sw[lk4 + 0][row] = v.x;
            sw[lk4 + 1][row] = v.y;
            sw[lk4 + 2][row] = v.z;
            sw[lk4 + 3][row] = v.w;
        }
        __syncthreads();

        #pragma unroll 8
        for (int k = 0; k < BK; k++) {
            unsigned long long xp[4];
            #pragma unroll
            for (int p = 0; p < 4; p++)
                xp[p] = *reinterpret_cast<const unsigned long long*>(&sx[k][m0 + 2 * p]);

            float4 wv = *reinterpret_cast<const float4*>(&sw[k][n0]);
            unsigned long long wd[4];
            unsigned int wb;
            wb = __float_as_uint(wv.x); asm("mov.b64 %0,{%1,%1};" : "=l"(wd[0]) : "r"(wb));
            wb = __float_as_uint(wv.y); asm("mov.b64 %0,{%1,%1};" : "=l"(wd[1]) : "r"(wb));
            wb = __float_as_uint(wv.z); asm("mov.b64 %0,{%1,%1};" : "=l"(wd[2]) : "r"(wb));
            wb = __float_as_uint(wv.w); asm("mov.b64 %0,{%1,%1};" : "=l"(wd[3]) : "r"(wb));

            #pragma unroll
            for (int j = 0; j < 4; j++)
                #pragma unroll
                for (int p = 0; p < 4; p++)
                    asm("fma.rn.f32x2 %0, %1, %2, %0;"
                        : "+l"(acc[j][p]) : "l"(xp[p]), "l"(wd[j]));
        }
        __syncthreads();
    }

    // ---- spill accumulators to smem logits tile ----
    #pragma unroll
    for (int j = 0; j < 4; j++) {
        #pragma unroll
        for (int p = 0; p < 4; p++) {
            unsigned int lo, hi;
            asm("mov.b64 {%0,%1}, %2;" : "=r"(lo), "=r"(hi) : "l"(acc[j][p]));
            slog[m0 + 2 * p    ][n0 + j] = __uint_as_float(lo);
            slog[m0 + 2 * p + 1][n0 + j] = __uint_as_float(hi);
        }
    }
    __syncthreads();

    // ---- per-token epilogue: top-2 (jax tie order: lowest index first), softmax, logsumexp ----
    if (tid < BM) {
        float m1 = -3.402823466e38f, m2 = -3.402823466e38f;
        int i1 = 0, i2 = 0;
        #pragma unroll
        for (int e = 0; e < NE; e++) {
            float v = slog[tid][e];
            if (v > m1)      { m2 = m1; i2 = i1; m1 = v; i1 = e; }
            else if (v > m2) { m2 = v;  i2 = e; }
        }
        float sum = 0.f;
        #pragma unroll
        for (int e = 0; e < NE; e++) sum += expf(slog[tid][e] - m1);
        float lz = m1 + logf(sum);
        out_loss[m_base + tid] = lz * lz;

        float d  = expf(m2 - m1);
        float s1 = 1.f / (1.f + d);
        s_s1[tid] = s1;
        s_s2[tid] = d * s1;
        s_i1[tid] = i1;
        s_i2[tid] = i2;
    }
    __syncthreads();

    // ---- coalesced stores of logits + scattered top-2 scores ----
    float* lg = out_logits + (size_t)m_base * NE;
    float* sc = out_scores + (size_t)m_base * NE;
    for (int idx = tid; idx < BM * NE; idx += NTHR) {
        int t = idx >> 6;
        int e = idx & 63;
        lg[idx] = slog[t][e];
        float sv = (e == s_i1[t]) ? s_s1[t] : ((e == s_i2[t]) ? s_s2[t] : 0.f);
        sc[idx] = sv;
    }
}

extern "C" void kernel_launch(void* const* d_in, const int* in_sizes, int n_in,
                              void* d_out, int out_size)
{
    const float* x = (const float*)d_in[0];
    const float* W = (const float*)d_in[1];
    float* out    = (float*)d_out;
    float* logits = out;
    float* scores = out + (size_t)TOKENS * NE;
    float* loss   = out + (size_t)2 * TOKENS * NE;

    topk_gate_kernel<<<TOKENS / BM, NTHR>>>(x, W, logits, scores, loss);
}

// round 3
// speedup vs baseline: 1.8577x; 1.8577x over previous
#include <cuda_runtime.h>
#include <stdint.h>

#define TOKENS 16384
#define DIM    4096
#define NE     64
#define BM     128
#define BK     64
#define NITER  (DIM / BK)    // 64
#define NTHR   256

// per-stage smem layout (bytes): bf16 tiles, 128B row stride (64 bf16)
#define XH_OFF 0          // 128 x 64 bf16 = 16KB
#define XL_OFF 16384
#define WH_OFF 32768      // 64 x 64 bf16 = 8KB
#define WL_OFF 40960
#define STAGE  49152
#define SMEM_TOTAL (2 * STAGE)   // 96KB

__device__ __forceinline__ uint32_t smem_u32(const void* p) {
    uint32_t a;
    asm("{ .reg .u64 t; cvta.to.shared.u64 t, %1; cvt.u32.u64 %0, t; }"
        : "=r"(a) : "l"(p));
    return a;
}

// fp32 -> (bf16 hi, bf16 lo) split; packs (f0 low, f1 high) halves
__device__ __forceinline__ void cvt_pair(float f0, float f1, uint32_t& h, uint32_t& l) {
    asm("cvt.rn.bf16x2.f32 %0, %1, %2;" : "=r"(h) : "f"(f1), "f"(f0));
    float hf0 = __uint_as_float(h << 16);
    float hf1 = __uint_as_float(h & 0xffff0000u);
    float r0 = f0 - hf0;
    float r1 = f1 - hf1;
    asm("cvt.rn.bf16x2.f32 %0, %1, %2;" : "=r"(l) : "f"(r1), "f"(r0));
}

__device__ __forceinline__ void ldsm4(uint32_t addr, uint32_t r[4]) {
    asm volatile("ldmatrix.sync.aligned.m8n8.x4.shared.b16 {%0,%1,%2,%3}, [%4];"
        : "=r"(r[0]), "=r"(r[1]), "=r"(r[2]), "=r"(r[3]) : "r"(addr));
}

__device__ __forceinline__ void mma16816(float c[4], const uint32_t a[4],
                                         uint32_t b0, uint32_t b1) {
    asm volatile(
        "mma.sync.aligned.m16n8k16.row.col.f32.bf16.bf16.f32 "
        "{%0,%1,%2,%3}, {%4,%5,%6,%7}, {%8,%9}, {%0,%1,%2,%3};"
        : "+f"(c[0]), "+f"(c[1]), "+f"(c[2]), "+f"(c[3])
        : "r"(a[0]), "r"(a[1]), "r"(a[2]), "r"(a[3]), "r"(b0), "r"(b1));
}

__global__ __launch_bounds__(NTHR, 1)
void topk_gate_hmma(const float* __restrict__ x, const float* __restrict__ W,
                    float* __restrict__ out_logits, float* __restrict__ out_scores,
                    float* __restrict__ out_loss)
{
    extern __shared__ char smem[];
    const uint32_t sbase = smem_u32(smem);

    const int tid  = threadIdx.x;
    const int lane = tid & 31;
    const int wid  = tid >> 5;
    const int warp_m = wid >> 1;     // 0..3 -> m offset *32
    const int warp_n = wid & 1;      // 0..1 -> n offset *32
    const size_t m_base = (size_t)blockIdx.x * BM;

    // ldmatrix lane geometry (rows share low-3 bits with lane -> swizzle is lane-only)
    const int laneRowA = (lane & 7) + ((lane >> 3) & 1) * 8;
    const int laneKbA  = ((lane >> 4) & 1) * 16;
    const int laneRowB = (lane & 7) + ((lane >> 4) & 1) * 8;
    const int laneKbB  = ((lane >> 3) & 1) * 16;
    const int swz      = (lane & 7) << 4;

    float acc[2][4][4];
    #pragma unroll
    for (int mg = 0; mg < 2; mg++)
        #pragma unroll
        for (int nt = 0; nt < 4; nt++)
            #pragma unroll
            for (int q = 0; q < 4; q++) acc[mg][nt][q] = 0.f;

    const float* xg = x + m_base * DIM;

    // LDG register buffers: x 4 tasks x 8 floats, W 2 tasks x 8 floats
    float4 rx[8];
    float4 rw[4];

    const int xrow = tid >> 3;             // base task mapping
    const int xkc  = (tid & 7) * 8;

    // ---------------- pipeline helpers as macros ----------------
#define LDG_STAGE(K0)                                                          \
    do {                                                                       \
        _Pragma("unroll")                                                      \
        for (int i = 0; i < 4; i++) {                                          \
            int row = xrow + i * 32;                                           \
            const float* p = xg + (size_t)row * DIM + (K0) + xkc;              \
            rx[2*i]   = *reinterpret_cast<const float4*>(p);                   \
            rx[2*i+1] = *reinterpret_cast<const float4*>(p + 4);               \
        }                                                                      \
        _Pragma("unroll")                                                      \
        for (int i = 0; i < 2; i++) {                                          \
            int row = xrow + i * 32;                                           \
            const float* p = W + (size_t)row * DIM + (K0) + xkc;               \
            rw[2*i]   = *reinterpret_cast<const float4*>(p);                   \
            rw[2*i+1] = *reinterpret_cast<const float4*>(p + 4);               \
        }                                                                      \
    } while (0)

#define STS_STAGE(S)                                                           \
    do {                                                                       \
        char* bufp = smem + (S) * STAGE;                                       \
        int off = ((xkc * 2) ^ ((xrow & 7) << 4));                             \
        _Pragma("unroll")                                                      \
        for (int i = 0; i < 4; i++) {                                          \
            int row = xrow + i * 32;                                           \
            uint4 h, l;                                                        \
            cvt_pair(rx[2*i].x,   rx[2*i].y,   h.x, l.x);                      \
            cvt_pair(rx[2*i].z,   rx[2*i].w,   h.y, l.y);                      \
            cvt_pair(rx[2*i+1].x, rx[2*i+1].y, h.z, l.z);                      \
            cvt_pair(rx[2*i+1].z, rx[2*i+1].w, h.w, l.w);                      \
            *reinterpret_cast<uint4*>(bufp + XH_OFF + row * 128 + off) = h;    \
            *reinterpret_cast<uint4*>(bufp + XL_OFF + row * 128 + off) = l;    \
        }                                                                      \
        _Pragma("unroll")                                                      \
        for (int i = 0; i < 2; i++) {                                          \
            int row = xrow + i * 32;                                           \
            uint4 h, l;                                                        \
            cvt_pair(rw[2*i].x,   rw[2*i].y,   h.x, l.x);                      \
            cvt_pair(rw[2*i].z,   rw[2*i].w,   h.y, l.y);                      \
            cvt_pair(rw[2*i+1].x, rw[2*i+1].y, h.z, l.z);                      \
            cvt_pair(rw[2*i+1].z, rw[2*i+1].w, h.w, l.w);                      \
            *reinterpret_cast<uint4*>(bufp + WH_OFF + row * 128 + off) = h;    \
            *reinterpret_cast<uint4*>(bufp + WL_OFF + row * 128 + off) = l;    \
        }                                                                      \
    } while (0)

    // prologue: stage 0
    LDG_STAGE(0);
    STS_STAGE(0);

    const uint32_t rowA0 = (uint32_t)(warp_m * 32 + laneRowA) * 128u;
    const uint32_t rowB0 = (uint32_t)(warp_n * 32 + laneRowB) * 128u;

    for (int it = 0; it < NITER; ++it) {
        __syncthreads();
        const int s = it & 1;
        const uint32_t xb = sbase + (uint32_t)s * STAGE;

        if (it + 1 < NITER) LDG_STAGE((it + 1) * BK);

        // ---- compute 4 k16-steps on stage s ----
        #pragma unroll
        for (int j = 0; j < 4; j++) {
            const uint32_t coA = (uint32_t)(((j << 5) | laneKbA) ^ swz);
            const uint32_t coB = (uint32_t)(((j << 5) | laneKbB) ^ swz);

            uint32_t ah[2][4], al[2][4];
            #pragma unroll
            for (int mg = 0; mg < 2; mg++) {
                uint32_t ra = xb + rowA0 + (uint32_t)(mg * 16 * 128);
                ldsm4(ra + XH_OFF + coA, ah[mg]);
                ldsm4(ra + XL_OFF + coA, al[mg]);
            }
            uint32_t bh[2][4], bl[2][4];
            #pragma unroll
            for (int ng = 0; ng < 2; ng++) {
                uint32_t rb = xb + rowB0 + (uint32_t)(ng * 16 * 128);
                ldsm4(rb + WH_OFF + coB, bh[ng]);
                ldsm4(rb + WL_OFF + coB, bl[ng]);
            }
            #pragma unroll
            for (int mg = 0; mg < 2; mg++) {
                #pragma unroll
                for (int nt = 0; nt < 4; nt++) {
                    const int ng = nt >> 1;
                    const int kb = (nt & 1) * 2;
                    mma16816(acc[mg][nt], ah[mg], bh[ng][kb], bh[ng][kb + 1]);
                    mma16816(acc[mg][nt], ah[mg], bl[ng][kb], bl[ng][kb + 1]);
                    mma16816(acc[mg][nt], al[mg], bh[ng][kb], bh[ng][kb + 1]);
                }
            }
        }

        if (it + 1 < NITER) STS_STAGE((it + 1) & 1);
    }

    // ---- epilogue: spill accs into logits tile at smem offset 0 (stage 0 free) ----
    float* slog = reinterpret_cast<float*>(smem);   // [128][65]
    const int gr = lane >> 2;          // 0..7
    const int gc = (lane & 3) * 2;
    #pragma unroll
    for (int mg = 0; mg < 2; mg++) {
        #pragma unroll
        for (int nt = 0; nt < 4; nt++) {
            int r0 = warp_m * 32 + mg * 16 + gr;
            int c  = warp_n * 32 + nt * 8 + gc;
            slog[r0 * 65 + c]           = acc[mg][nt][0];
            slog[r0 * 65 + c + 1]       = acc[mg][nt][1];
            slog[(r0 + 8) * 65 + c]     = acc[mg][nt][2];
            slog[(r0 + 8) * 65 + c + 1] = acc[mg][nt][3];
        }
    }

    float* s_s1 = reinterpret_cast<float*>(smem + 33280);
    float* s_s2 = s_s1 + 128;
    int*   s_i1 = reinterpret_cast<int*>(s_s2 + 128);
    int*   s_i2 = s_i1 + 128;
    __syncthreads();

    if (tid < BM) {
        const float* r = slog + tid * 65;
        float m1 = -3.402823466e38f, m2 = -3.402823466e38f;
        int i1 = 0, i2 = 0;
        #pragma unroll
        for (int e = 0; e < NE; e++) {
            float v = r[e];
            if (v > m1)      { m2 = m1; i2 = i1; m1 = v; i1 = e; }
            else if (v > m2) { m2 = v;  i2 = e; }
        }
        float sum = 0.f;
        #pragma unroll
        for (int e = 0; e < NE; e++) sum += expf(r[e] - m1);
        float lz = m1 + logf(sum);
        out_loss[m_base + tid] = lz * lz;

        float dd = expf(m2 - m1);
        float s1 = 1.f / (1.f + dd);
        s_s1[tid] = s1;
        s_s2[tid] = dd * s1;
        s_i1[tid] = i1;
        s_i2[tid] = i2;
    }
    __syncthreads();

    float* lg = out_logits + m_base * NE;
    float* sc = out_scores + m_base * NE;
    for (int idx = tid; idx < BM * NE; idx += NTHR) {
        int t = idx >> 6;
        int e = idx & 63;
        lg[idx] = slog[t * 65 + e];
        float sv = (e == s_i1[t]) ? s_s1[t] : ((e == s_i2[t]) ? s_s2[t] : 0.f);
        sc[idx] = sv;
    }
#undef LDG_STAGE
#undef STS_STAGE
}

extern "C" void kernel_launch(void* const* d_in, const int* in_sizes, int n_in,
                              void* d_out, int out_size)
{
    const float* x = (const float*)d_in[0];
    const float* W = (const float*)d_in[1];
    float* out    = (float*)d_out;
    float* logits = out;
    float* scores = out + (size_t)TOKENS * NE;
    float* loss   = out + (size_t)2 * TOKENS * NE;

    cudaFuncSetAttribute(topk_gate_hmma,
                         cudaFuncAttributeMaxDynamicSharedMemorySize, SMEM_TOTAL);
    topk_gate_hmma<<<TOKENS / BM, NTHR, SMEM_TOTAL>>>(x, W, logits, scores, loss);
}

// round 4
// speedup vs baseline: 2.6125x; 1.4063x over previous
#include <cuda_runtime.h>
#include <stdint.h>

#define TOKENS 16384
#define DIM    4096
#define NE     64
#define BM     64
#define BK     64
#define NITER  (DIM / BK)    // 64
#define NTHR   256

// per-stage smem (bytes): x tile only, bf16 hi/lo, 128B row stride
#define XH_OFF  0            // 64 x 64 bf16 = 8KB
#define XL_OFF  8192
#define STAGE   16384
// epilogue regions (reused after GEMM):
#define SLOG_OFF 0           // 64 x 65 fp32 = 16640B
#define RED_OFF  16640       // 4 pos x 32 lane x 32 fp32 = 16384B
#define S1_OFF   33024
#define S2_OFF   33280
#define I1_OFF   33536
#define I2_OFF   33792
#define SMEM_TOTAL 34816

// W in B-fragment order: [kstep j 0..255][nblk 0..7][lane 0..31] -> uint4{b0h,b1h,b0l,b1l}
__device__ __align__(16) uint4 g_wfrag[256 * 8 * 32];

__device__ __forceinline__ uint32_t smem_u32(const void* p) {
    uint32_t a;
    asm("{ .reg .u64 t; cvta.to.shared.u64 t, %1; cvt.u32.u64 %0, t; }"
        : "=r"(a) : "l"(p));
    return a;
}

// fp32 -> (bf16 hi, bf16 lo); packed bf16x2 (f0 -> low half, f1 -> high half)
__device__ __forceinline__ void cvt_pair(float f0, float f1, uint32_t& h, uint32_t& l) {
    asm("cvt.rn.bf16x2.f32 %0, %1, %2;" : "=r"(h) : "f"(f1), "f"(f0));
    float hf0 = __uint_as_float(h << 16);
    float hf1 = __uint_as_float(h & 0xffff0000u);
    float r0 = f0 - hf0;
    float r1 = f1 - hf1;
    asm("cvt.rn.bf16x2.f32 %0, %1, %2;" : "=r"(l) : "f"(r1), "f"(r0));
}

__device__ __forceinline__ void ldsm4(uint32_t addr, uint32_t r[4]) {
    asm volatile("ldmatrix.sync.aligned.m8n8.x4.shared.b16 {%0,%1,%2,%3}, [%4];"
        : "=r"(r[0]), "=r"(r[1]), "=r"(r[2]), "=r"(r[3]) : "r"(addr));
}

__device__ __forceinline__ void mma16816(float c[4], const uint32_t a[4],
                                         uint32_t b0, uint32_t b1) {
    asm volatile(
        "mma.sync.aligned.m16n8k16.row.col.f32.bf16.bf16.f32 "
        "{%0,%1,%2,%3}, {%4,%5,%6,%7}, {%8,%9}, {%0,%1,%2,%3};"
        : "+f"(c[0]), "+f"(c[1]), "+f"(c[2]), "+f"(c[3])
        : "r"(a[0]), "r"(a[1]), "r"(a[2]), "r"(a[3]), "r"(b0), "r"(b1));
}

// ---------------- prep: W fp32 -> bf16 hi/lo in mma-B-fragment order ----------------
__global__ void prep_w(const float* __restrict__ W) {
    int idx = blockIdx.x * 256 + threadIdx.x;      // 0..65535
    int j    = idx >> 8;                           // kstep 0..255
    int lane = idx & 31;
    int nb   = (idx >> 5) & 7;
    int n = nb * 8 + (lane >> 2);
    int k = j * 16 + (lane & 3) * 2;
    const float* p = W + (size_t)n * DIM + k;
    float f0 = p[0], f1 = p[1], f2 = p[8], f3 = p[9];
    uint32_t h0, l0, h1, l1;
    cvt_pair(f0, f1, h0, l0);
    cvt_pair(f2, f3, h1, l1);
    g_wfrag[idx] = make_uint4(h0, h1, l0, l1);
}

// ---------------- main fused kernel ----------------
__global__ __launch_bounds__(NTHR, 2)
void topk_gate_hmma2(const float* __restrict__ x,
                     float* __restrict__ out_logits, float* __restrict__ out_scores,
                     float* __restrict__ out_loss)
{
    extern __shared__ char smem[];
    const uint32_t sbase = smem_u32(smem);

    const int tid  = threadIdx.x;
    const int lane = tid & 31;
    const int wid  = tid >> 5;
    const int pos    = wid >> 1;        // 0..3 output quadrant
    const int ks     = wid & 1;         // k-slice 0/1
    const int warp_m = pos >> 1;        // m offset *32
    const int warp_n = pos & 1;         // n offset *32
    const size_t m_base = (size_t)blockIdx.x * BM;

    // ldmatrix lane geometry for A (proven in R3)
    const int laneRowA = (lane & 7) + ((lane >> 3) & 1) * 8;
    const int laneKbA  = ((lane >> 4) & 1) * 16;
    const int swz      = (lane & 7) << 4;
    const uint32_t rowA0 = (uint32_t)(warp_m * 32 + laneRowA) * 128u;

    float acc[2][4][4];
    #pragma unroll
    for (int mg = 0; mg < 2; mg++)
        #pragma unroll
        for (int nt = 0; nt < 4; nt++)
            #pragma unroll
            for (int q = 0; q < 4; q++) acc[mg][nt][q] = 0.f;

    const float* xg = x + m_base * DIM;
    const int xrow = tid >> 2;           // 0..63
    const int xkc  = (tid & 3) * 16;     // k-col base (floats)

    float4 rx[4];

#define LDG_X(K0)                                                              \
    do {                                                                       \
        const float* p = xg + (size_t)xrow * DIM + (K0) + xkc;                 \
        rx[0] = *reinterpret_cast<const float4*>(p);                           \
        rx[1] = *reinterpret_cast<const float4*>(p + 4);                       \
        rx[2] = *reinterpret_cast<const float4*>(p + 8);                       \
        rx[3] = *reinterpret_cast<const float4*>(p + 12);                      \
    } while (0)

#define STS_X(S)                                                               \
    do {                                                                       \
        char* bufp = smem + (S) * STAGE;                                       \
        _Pragma("unroll")                                                      \
        for (int c = 0; c < 4; c++) {                                          \
            uint32_t h01, l01, h23, l23;                                       \
            cvt_pair(rx[c].x, rx[c].y, h01, l01);                              \
            cvt_pair(rx[c].z, rx[c].w, h23, l23);                              \
            int kbyte = xkc * 2 + c * 8;                                       \
            int off = xrow * 128 + (kbyte ^ ((xrow & 7) << 4));                \
            *reinterpret_cast<uint2*>(bufp + XH_OFF + off) = make_uint2(h01, h23); \
            *reinterpret_cast<uint2*>(bufp + XL_OFF + off) = make_uint2(l01, l23); \
        }                                                                      \
    } while (0)

    // prologue
    LDG_X(0);
    STS_X(0);

    for (int it = 0; it < NITER; ++it) {
        __syncthreads();
        const int s = it & 1;
        const uint32_t xb = sbase + (uint32_t)s * STAGE;

        if (it + 1 < NITER) LDG_X((it + 1) * BK);

        // ---- this warp's two k16-steps ----
        const int jbase = it * 4 + ks * 2;

        // B fragments for kstep 0 (4 n8-blocks)
        uint4 b0[4], b1[4];
        {
            const uint4* wp = g_wfrag + ((size_t)(jbase * 8 + warp_n * 4) * 32 + lane);
            #pragma unroll
            for (int nt = 0; nt < 4; nt++) b0[nt] = wp[nt * 32];
            #pragma unroll
            for (int nt = 0; nt < 4; nt++) b1[nt] = wp[8 * 32 + nt * 32];
        }

        #pragma unroll
        for (int jj = 0; jj < 2; jj++) {
            const int j = ks * 2 + jj;
            const uint32_t coA = (uint32_t)(((j << 5) | laneKbA) ^ swz);
            uint32_t ah[2][4], al[2][4];
            #pragma unroll
            for (int mg = 0; mg < 2; mg++) {
                uint32_t ra = xb + rowA0 + (uint32_t)(mg * 16 * 128);
                ldsm4(ra + XH_OFF + coA, ah[mg]);
                ldsm4(ra + XL_OFF + coA, al[mg]);
            }
            #pragma unroll
            for (int mg = 0; mg < 2; mg++) {
                #pragma unroll
                for (int nt = 0; nt < 4; nt++) {
                    const uint4 q = jj ? b1[nt] : b0[nt];
                    mma16816(acc[mg][nt], ah[mg], q.x, q.y);  // hi*hi
                    mma16816(acc[mg][nt], ah[mg], q.z, q.w);  // hi*lo
                    mma16816(acc[mg][nt], al[mg], q.x, q.y);  // lo*hi
                }
            }
        }

        if (it + 1 < NITER) STS_X((it + 1) & 1);
    }

    __syncthreads();   // all mma reads of smem stages done

    // ---- k-slice reduction: ks=1 warps dump accs, ks=0 warps add ----
    float* red = reinterpret_cast<float*>(smem + RED_OFF);
    if (ks == 1) {
        float* rp = red + (pos * 32 + lane) * 32;
        #pragma unroll
        for (int mg = 0; mg < 2; mg++)
            #pragma unroll
            for (int nt = 0; nt < 4; nt++)
                #pragma unroll
                for (int q = 0; q < 4; q++)
                    rp[mg * 16 + nt * 4 + q] = acc[mg][nt][q];
    }
    __syncthreads();

    float* slog = reinterpret_cast<float*>(smem + SLOG_OFF);   // [64][65]
    if (ks == 0) {
        const float* rp = red + (pos * 32 + lane) * 32;
        const int gr = lane >> 2;
        const int gc = (lane & 3) * 2;
        #pragma unroll
        for (int mg = 0; mg < 2; mg++) {
            #pragma unroll
            for (int nt = 0; nt < 4; nt++) {
                float c0 = acc[mg][nt][0] + rp[mg * 16 + nt * 4 + 0];
                float c1 = acc[mg][nt][1] + rp[mg * 16 + nt * 4 + 1];
                float c2 = acc[mg][nt][2] + rp[mg * 16 + nt * 4 + 2];
                float c3 = acc[mg][nt][3] + rp[mg * 16 + nt * 4 + 3];
                int r0 = warp_m * 32 + mg * 16 + gr;
                int cc = warp_n * 32 + nt * 8 + gc;
                slog[r0 * 65 + cc]           = c0;
                slog[r0 * 65 + cc + 1]       = c1;
                slog[(r0 + 8) * 65 + cc]     = c2;
                slog[(r0 + 8) * 65 + cc + 1] = c3;
            }
        }
    }
    __syncthreads();

    float* s_s1 = reinterpret_cast<float*>(smem + S1_OFF);
    float* s_s2 = reinterpret_cast<float*>(smem + S2_OFF);
    int*   s_i1 = reinterpret_cast<int*>(smem + I1_OFF);
    int*   s_i2 = reinterpret_cast<int*>(smem + I2_OFF);

    if (tid < BM) {
        const float* r = slog + tid * 65;
        float m1 = -3.402823466e38f, m2 = -3.402823466e38f;
        int i1 = 0, i2 = 0;
        #pragma unroll
        for (int e = 0; e < NE; e++) {
            float v = r[e];
            if (v > m1)      { m2 = m1; i2 = i1; m1 = v; i1 = e; }
            else if (v > m2) { m2 = v;  i2 = e; }
        }
        float sum = 0.f;
        #pragma unroll
        for (int e = 0; e < NE; e++) sum += expf(r[e] - m1);
        float lz = m1 + logf(sum);
        out_loss[m_base + tid] = lz * lz;

        float dd = expf(m2 - m1);
        float s1 = 1.f / (1.f + dd);
        s_s1[tid] = s1;
        s_s2[tid] = dd * s1;
        s_i1[tid] = i1;
        s_i2[tid] = i2;
    }
    __syncthreads();

    float* lg = out_logits + m_base * NE;
    float* sc = out_scores + m_base * NE;
    #pragma unroll
    for (int pass = 0; pass < (BM * NE) / NTHR; pass++) {
        int idx = pass * NTHR + tid;
        int t = idx >> 6;
        int e = idx & 63;
        lg[idx] = slog[t * 65 + e];
        float sv = (e == s_i1[t]) ? s_s1[t] : ((e == s_i2[t]) ? s_s2[t] : 0.f);
        sc[idx] = sv;
    }
#undef LDG_X
#undef STS_X
}

extern "C" void kernel_launch(void* const* d_in, const int* in_sizes, int n_in,
                              void* d_out, int out_size)
{
    const float* x = (const float*)d_in[0];
    const float* W = (const float*)d_in[1];
    float* out    = (float*)d_out;
    float* logits = out;
    float* scores = out + (size_t)TOKENS * NE;
    float* loss   = out + (size_t)2 * TOKENS * NE;

    prep_w<<<256, 256>>>(W);

    cudaFuncSetAttribute(topk_gate_hmma2,
                         cudaFuncAttributeMaxDynamicSharedMemorySize, SMEM_TOTAL);
    topk_gate_hmma2<<<TOKENS / BM, NTHR, SMEM_TOTAL>>>(x, logits, scores, loss);
}

// round 5
// speedup vs baseline: 2.6719x; 1.0227x over previous
#include <cuda_runtime.h>
#include <stdint.h>

#define TOKENS 16384
#define DIM    4096
#define NE     64
#define BM     64
#define NITER  64          // k chunks of 64
#define NTHR   256

// W in B-fragment order: [kstep j 0..255][nblk 0..7][lane 0..31] -> uint4{b0h,b1h,b0l,b1l}
__device__ __align__(16) uint4 g_wfrag[256 * 8 * 32];

// fp32 -> (bf16 hi, bf16 lo); packed bf16x2 (f0 -> low half, f1 -> high half)
__device__ __forceinline__ void cvt_pair(float f0, float f1, uint32_t& h, uint32_t& l) {
    asm("cvt.rn.bf16x2.f32 %0, %1, %2;" : "=r"(h) : "f"(f1), "f"(f0));
    float hf0 = __uint_as_float(h << 16);
    float hf1 = __uint_as_float(h & 0xffff0000u);
    float r0 = f0 - hf0;
    float r1 = f1 - hf1;
    asm("cvt.rn.bf16x2.f32 %0, %1, %2;" : "=r"(l) : "f"(r1), "f"(r0));
}

__device__ __forceinline__ void mma16816(float c[4], const uint32_t a[4],
                                         uint32_t b0, uint32_t b1) {
    asm volatile(
        "mma.sync.aligned.m16n8k16.row.col.f32.bf16.bf16.f32 "
        "{%0,%1,%2,%3}, {%4,%5,%6,%7}, {%8,%9}, {%0,%1,%2,%3};"
        : "+f"(c[0]), "+f"(c[1]), "+f"(c[2]), "+f"(c[3])
        : "r"(a[0]), "r"(a[1]), "r"(a[2]), "r"(a[3]), "r"(b0), "r"(b1));
}

// ---------------- prep: W fp32 -> bf16 hi/lo in mma-B-fragment order ----------------
__global__ void prep_w(const float* __restrict__ W) {
    int idx = blockIdx.x * 256 + threadIdx.x;      // 0..65535
    int j    = idx >> 8;                           // kstep 0..255
    int lane = idx & 31;
    int nb   = (idx >> 5) & 7;
    int n = nb * 8 + (lane >> 2);
    int k = j * 16 + (lane & 3) * 2;
    const float* p = W + (size_t)n * DIM + k;
    float f0 = p[0], f1 = p[1], f2 = p[8], f3 = p[9];
    uint32_t h0, l0, h1, l1;
    cvt_pair(f0, f1, h0, l0);
    cvt_pair(f2, f3, h1, l1);
    g_wfrag[idx] = make_uint4(h0, h1, l0, l1);
}

// ---------------- main fused kernel: no smem in mainloop ----------------
__global__ __launch_bounds__(NTHR, 2)
void topk_gate_hmma3(const float* __restrict__ x,
                     float* __restrict__ out_logits, float* __restrict__ out_scores,
                     float* __restrict__ out_loss)
{
    __shared__ float slog[BM][NE + 1];
    __shared__ float red[4][32][32];
    __shared__ float s_s1[BM], s_s2[BM];
    __shared__ int   s_i1[BM], s_i2[BM];

    const int tid  = threadIdx.x;
    const int lane = tid & 31;
    const int wid  = tid >> 5;
    const int pos    = wid >> 1;        // 0..3 output quadrant
    const int ks     = wid & 1;         // k-slice 0/1
    const int warp_m = pos >> 1;        // m offset *32
    const int warp_n = pos & 1;         // n offset *32
    const size_t m_base = (size_t)blockIdx.x * BM;

    const float* xg = x + m_base * DIM;

    // A-fragment row pointers: [mg*2+rr] -> row warp_m*32 + mg*16 + (lane>>2) + rr*8,
    // column offset (lane&3)*2 baked in.
    const float* pA[4];
    #pragma unroll
    for (int mg = 0; mg < 2; mg++)
        #pragma unroll
        for (int rr = 0; rr < 2; rr++)
            pA[mg * 2 + rr] = xg
                + (size_t)(warp_m * 32 + mg * 16 + (lane >> 2) + rr * 8) * DIM
                + (lane & 3) * 2;

    float acc[2][4][4];
    #pragma unroll
    for (int mg = 0; mg < 2; mg++)
        #pragma unroll
        for (int nt = 0; nt < 4; nt++)
            #pragma unroll
            for (int q = 0; q < 4; q++) acc[mg][nt][q] = 0.f;

    for (int it = 0; it < NITER; ++it) {
        const int k0 = it * 64 + ks * 32;

        // ---- B fragments for both k16-steps of this warp's k32 slice ----
        uint4 qb[2][4];
        const uint4* wp = g_wfrag
            + ((size_t)((it * 4 + ks * 2) * 8 + warp_n * 4) * 32 + lane);
        #pragma unroll
        for (int nt = 0; nt < 4; nt++) {
            qb[0][nt] = wp[nt * 32];
            qb[1][nt] = wp[256 + nt * 32];
        }

        #pragma unroll
        for (int jj = 0; jj < 2; jj++) {
            // ---- A fragments direct from global (fragment order), fp32 ----
            float2 f[2][2][2];    // [mg][rr][kb]
            #pragma unroll
            for (int mg = 0; mg < 2; mg++)
                #pragma unroll
                for (int rr = 0; rr < 2; rr++)
                    #pragma unroll
                    for (int kb = 0; kb < 2; kb++)
                        f[mg][rr][kb] = *reinterpret_cast<const float2*>(
                            pA[mg * 2 + rr] + k0 + jj * 16 + kb * 8);

            uint32_t ah[2][4], al[2][4];
            #pragma unroll
            for (int mg = 0; mg < 2; mg++) {
                cvt_pair(f[mg][0][0].x, f[mg][0][0].y, ah[mg][0], al[mg][0]);
                cvt_pair(f[mg][1][0].x, f[mg][1][0].y, ah[mg][1], al[mg][1]);
                cvt_pair(f[mg][0][1].x, f[mg][0][1].y, ah[mg][2], al[mg][2]);
                cvt_pair(f[mg][1][1].x, f[mg][1][1].y, ah[mg][3], al[mg][3]);
            }

            #pragma unroll
            for (int mg = 0; mg < 2; mg++) {
                #pragma unroll
                for (int nt = 0; nt < 4; nt++) {
                    const uint4 q = qb[jj][nt];
                    mma16816(acc[mg][nt], ah[mg], q.x, q.y);  // hi*hi
                    mma16816(acc[mg][nt], ah[mg], q.z, q.w);  // hi*lo
                    mma16816(acc[mg][nt], al[mg], q.x, q.y);  // lo*hi
                }
            }
        }
    }

    // ---- k-slice reduction: ks=1 warps dump accs, ks=0 warps add ----
    if (ks == 1) {
        float* rp = &red[pos][lane][0];
        #pragma unroll
        for (int mg = 0; mg < 2; mg++)
            #pragma unroll
            for (int nt = 0; nt < 4; nt++)
                #pragma unroll
                for (int q = 0; q < 4; q++)
                    rp[mg * 16 + nt * 4 + q] = acc[mg][nt][q];
    }
    __syncthreads();

    if (ks == 0) {
        const float* rp = &red[pos][lane][0];
        const int gr = lane >> 2;
        const int gc = (lane & 3) * 2;
        #pragma unroll
        for (int mg = 0; mg < 2; mg++) {
            #pragma unroll
            for (int nt = 0; nt < 4; nt++) {
                float c0 = acc[mg][nt][0] + rp[mg * 16 + nt * 4 + 0];
                float c1 = acc[mg][nt][1] + rp[mg * 16 + nt * 4 + 1];
                float c2 = acc[mg][nt][2] + rp[mg * 16 + nt * 4 + 2];
                float c3 = acc[mg][nt][3] + rp[mg * 16 + nt * 4 + 3];
                int r0 = warp_m * 32 + mg * 16 + gr;
                int cc = warp_n * 32 + nt * 8 + gc;
                slog[r0][cc]         = c0;
                slog[r0][cc + 1]     = c1;
                slog[r0 + 8][cc]     = c2;
                slog[r0 + 8][cc + 1] = c3;
            }
        }
    }
    __syncthreads();

    if (tid < BM) {
        const float* r = &slog[tid][0];
        float m1 = -3.402823466e38f, m2 = -3.402823466e38f;
        int i1 = 0, i2 = 0;
        #pragma unroll
        for (int e = 0; e < NE; e++) {
            float v = r[e];
            if (v > m1)      { m2 = m1; i2 = i1; m1 = v; i1 = e; }
            else if (v > m2) { m2 = v;  i2 = e; }
        }
        float sum = 0.f;
        #pragma unroll
        for (int e = 0; e < NE; e++) sum += expf(r[e] - m1);
        float lz = m1 + logf(sum);
        out_loss[m_base + tid] = lz * lz;

        float dd = expf(m2 - m1);
        float s1 = 1.f / (1.f + dd);
        s_s1[tid] = s1;
        s_s2[tid] = dd * s1;
        s_i1[tid] = i1;
        s_i2[tid] = i2;
    }
    __syncthreads();

    float* lg = out_logits + m_base * NE;
    float* sc = out_scores + m_base * NE;
    #pragma unroll
    for (int pass = 0; pass < (BM * NE) / NTHR; pass++) {
        int idx = pass * NTHR + tid;
        int t = idx >> 6;
        int e = idx & 63;
        lg[idx] = slog[t][e];
        float sv = (e == s_i1[t]) ? s_s1[t] : ((e == s_i2[t]) ? s_s2[t] : 0.f);
        sc[idx] = sv;
    }
}

extern "C" void kernel_launch(void* const* d_in, const int* in_sizes, int n_in,
                              void* d_out, int out_size)
{
    const float* x = (const float*)d_in[0];
    const float* W = (const float*)d_in[1];
    float* out    = (float*)d_out;
    float* logits = out;
    float* scores = out + (size_t)TOKENS * NE;
    float* loss   = out + (size_t)2 * TOKENS * NE;

    prep_w<<<256, 256>>>(W);
    topk_gate_hmma3<<<TOKENS / BM, NTHR>>>(x, logits, scores, loss);
}

// round 6
// speedup vs baseline: 2.7935x; 1.0455x over previous
#include <cuda_runtime.h>
#include <stdint.h>

#define TOKENS 16384
#define DIM    4096
#define NE     64
#define BM     64
#define NITER  64          // k chunks of 64
#define NTHR   256

// W in B-fragment order with k-permutation: fragment for kstep j, lane t=lane&3
// holds W cols j*16 + 4t .. 4t+3 (mapped to mma kappa slots 2t,2t+1,8+2t,8+2t+1).
// layout: [kstep j 0..255][nblk 0..7][lane 0..31] -> uint4{b0h,b1h,b0l,b1l}
__device__ __align__(16) uint4 g_wfrag[256 * 8 * 32];

// fp32 -> (bf16 hi, bf16 lo); packed bf16x2 (f0 -> low half, f1 -> high half)
__device__ __forceinline__ void cvt_pair(float f0, float f1, uint32_t& h, uint32_t& l) {
    asm("cvt.rn.bf16x2.f32 %0, %1, %2;" : "=r"(h) : "f"(f1), "f"(f0));
    float hf0 = __uint_as_float(h << 16);
    float hf1 = __uint_as_float(h & 0xffff0000u);
    float r0 = f0 - hf0;
    float r1 = f1 - hf1;
    asm("cvt.rn.bf16x2.f32 %0, %1, %2;" : "=r"(l) : "f"(r1), "f"(r0));
}

__device__ __forceinline__ void mma16816(float c[4], const uint32_t a[4],
                                         uint32_t b0, uint32_t b1) {
    asm volatile(
        "mma.sync.aligned.m16n8k16.row.col.f32.bf16.bf16.f32 "
        "{%0,%1,%2,%3}, {%4,%5,%6,%7}, {%8,%9}, {%0,%1,%2,%3};"
        : "+f"(c[0]), "+f"(c[1]), "+f"(c[2]), "+f"(c[3])
        : "r"(a[0]), "r"(a[1]), "r"(a[2]), "r"(a[3]), "r"(b0), "r"(b1));
}

// ---------------- prep: W fp32 -> bf16 hi/lo, permuted-k fragment order ----------------
__global__ void prep_w(const float* __restrict__ W) {
    int idx = blockIdx.x * 256 + threadIdx.x;      // 0..65535
    int j    = idx >> 8;                           // kstep 0..255
    int lane = idx & 31;
    int nb   = (idx >> 5) & 7;
    int n = nb * 8 + (lane >> 2);
    int k = j * 16 + (lane & 3) * 4;               // 4 consecutive cols
    float4 v = *reinterpret_cast<const float4*>(W + (size_t)n * DIM + k);
    uint32_t h0, l0, h1, l1;
    cvt_pair(v.x, v.y, h0, l0);   // kappa slots 2t, 2t+1
    cvt_pair(v.z, v.w, h1, l1);   // kappa slots 8+2t, 8+2t+1
    g_wfrag[idx] = make_uint4(h0, h1, l0, l1);
}

// ---------------- main fused kernel: no smem in mainloop ----------------
__global__ __launch_bounds__(NTHR, 2)
void topk_gate_hmma4(const float* __restrict__ x,
                     float* __restrict__ out_logits, float* __restrict__ out_scores,
                     float* __restrict__ out_loss)
{
    __shared__ float slog[BM][NE + 1];
    __shared__ float red[4][32][32];
    __shared__ float s_s1[BM], s_s2[BM];
    __shared__ int   s_i1[BM], s_i2[BM];

    const int tid  = threadIdx.x;
    const int lane = tid & 31;
    const int wid  = tid >> 5;
    const int pos    = wid >> 1;        // 0..3 output quadrant
    const int ks     = wid & 1;         // k-slice 0/1
    const int warp_m = pos >> 1;        // m offset *32
    const int warp_n = pos & 1;         // n offset *32
    const size_t m_base = (size_t)blockIdx.x * BM;

    const float* xg = x + m_base * DIM;

    // A pointers: [mg*2+rr] -> row warp_m*32 + mg*16 + (lane>>2) + rr*8;
    // col base (lane&3)*4 + ks*32 baked in. One float4 per k16-step.
    const float* pA[4];
    #pragma unroll
    for (int mg = 0; mg < 2; mg++)
        #pragma unroll
        for (int rr = 0; rr < 2; rr++)
            pA[mg * 2 + rr] = xg
                + (size_t)(warp_m * 32 + mg * 16 + (lane >> 2) + rr * 8) * DIM
                + (lane & 3) * 4 + ks * 32;

    // B pointer: kstep jbase = ks*2, advances 4 per iteration (=1024 uint4)
    const uint4* wp = g_wfrag + ((size_t)((ks * 2) * 8 + warp_n * 4) * 32 + lane);

    float acc[2][4][4];
    #pragma unroll
    for (int mg = 0; mg < 2; mg++)
        #pragma unroll
        for (int nt = 0; nt < 4; nt++)
            #pragma unroll
            for (int q = 0; q < 4; q++) acc[mg][nt][q] = 0.f;

    int koff = 0;   // float offset within row for this iteration
    for (int it = 0; it < NITER; ++it, koff += 64, wp += 1024) {
        // ---- B fragments for both k16-steps of this warp's k32 slice ----
        uint4 qb[2][4];
        #pragma unroll
        for (int nt = 0; nt < 4; nt++) {
            qb[0][nt] = wp[nt * 32];
            qb[1][nt] = wp[256 + nt * 32];
        }

        #pragma unroll
        for (int jj = 0; jj < 2; jj++) {
            // ---- A: one float4 per pointer (permuted-k fragment) ----
            float4 v0 = *reinterpret_cast<const float4*>(pA[0] + koff + jj * 16);
            float4 v1 = *reinterpret_cast<const float4*>(pA[1] + koff + jj * 16);
            float4 v2 = *reinterpret_cast<const float4*>(pA[2] + koff + jj * 16);
            float4 v3 = *reinterpret_cast<const float4*>(pA[3] + koff + jj * 16);

            uint32_t ah[2][4], al[2][4];
            cvt_pair(v0.x, v0.y, ah[0][0], al[0][0]);
            cvt_pair(v1.x, v1.y, ah[0][1], al[0][1]);
            cvt_pair(v0.z, v0.w, ah[0][2], al[0][2]);
            cvt_pair(v1.z, v1.w, ah[0][3], al[0][3]);
            cvt_pair(v2.x, v2.y, ah[1][0], al[1][0]);
            cvt_pair(v3.x, v3.y, ah[1][1], al[1][1]);
            cvt_pair(v2.z, v2.w, ah[1][2], al[1][2]);
            cvt_pair(v3.z, v3.w, ah[1][3], al[1][3]);

            #pragma unroll
            for (int mg = 0; mg < 2; mg++) {
                #pragma unroll
                for (int nt = 0; nt < 4; nt++) {
                    const uint4 q = qb[jj][nt];
                    mma16816(acc[mg][nt], ah[mg], q.x, q.y);  // hi*hi
                    mma16816(acc[mg][nt], ah[mg], q.z, q.w);  // hi*lo
                    mma16816(acc[mg][nt], al[mg], q.x, q.y);  // lo*hi
                }
            }
        }
    }

    // ---- k-slice reduction: ks=1 warps dump accs, ks=0 warps add ----
    if (ks == 1) {
        float* rp = &red[pos][lane][0];
        #pragma unroll
        for (int mg = 0; mg < 2; mg++)
            #pragma unroll
            for (int nt = 0; nt < 4; nt++)
                #pragma unroll
                for (int q = 0; q < 4; q++)
                    rp[mg * 16 + nt * 4 + q] = acc[mg][nt][q];
    }
    __syncthreads();

    if (ks == 0) {
        const float* rp = &red[pos][lane][0];
        const int gr = lane >> 2;
        const int gc = (lane & 3) * 2;
        #pragma unroll
        for (int mg = 0; mg < 2; mg++) {
            #pragma unroll
            for (int nt = 0; nt < 4; nt++) {
                float c0 = acc[mg][nt][0] + rp[mg * 16 + nt * 4 + 0];
                float c1 = acc[mg][nt][1] + rp[mg * 16 + nt * 4 + 1];
                float c2 = acc[mg][nt][2] + rp[mg * 16 + nt * 4 + 2];
                float c3 = acc[mg][nt][3] + rp[mg * 16 + nt * 4 + 3];
                int r0 = warp_m * 32 + mg * 16 + gr;
                int cc = warp_n * 32 + nt * 8 + gc;
                slog[r0][cc]         = c0;
                slog[r0][cc + 1]     = c1;
                slog[r0 + 8][cc]     = c2;
                slog[r0 + 8][cc + 1] = c3;
            }
        }
    }
    __syncthreads();

    if (tid < BM) {
        const float* r = &slog[tid][0];
        float m1 = -3.402823466e38f, m2 = -3.402823466e38f;
        int i1 = 0, i2 = 0;
        #pragma unroll
        for (int e = 0; e < NE; e++) {
            float v = r[e];
            if (v > m1)      { m2 = m1; i2 = i1; m1 = v; i1 = e; }
            else if (v > m2) { m2 = v;  i2 = e; }
        }
        float sum = 0.f;
        #pragma unroll
        for (int e = 0; e < NE; e++) sum += expf(r[e] - m1);
        float lz = m1 + logf(sum);
        out_loss[m_base + tid] = lz * lz;

        float dd = expf(m2 - m1);
        float s1 = 1.f / (1.f + dd);
        s_s1[tid] = s1;
        s_s2[tid] = dd * s1;
        s_i1[tid] = i1;
        s_i2[tid] = i2;
    }
    __syncthreads();

    float* lg = out_logits + m_base * NE;
    float* sc = out_scores + m_base * NE;
    #pragma unroll
    for (int pass = 0; pass < (BM * NE) / NTHR; pass++) {
        int idx = pass * NTHR + tid;
        int t = idx >> 6;
        int e = idx & 63;
        lg[idx] = slog[t][e];
        float sv = (e == s_i1[t]) ? s_s1[t] : ((e == s_i2[t]) ? s_s2[t] : 0.f);
        sc[idx] = sv;
    }
}

extern "C" void kernel_launch(void* const* d_in, const int* in_sizes, int n_in,
                              void* d_out, int out_size)
{
    const float* x = (const float*)d_in[0];
    const float* W = (const float*)d_in[1];
    float* out    = (float*)d_out;
    float* logits = out;
    float* scores = out + (size_t)TOKENS * NE;
    float* loss   = out + (size_t)2 * TOKENS * NE;

    prep_w<<<256, 256>>>(W);
    topk_gate_hmma4<<<TOKENS / BM, NTHR>>>(x, logits, scores, loss);
}